// round 15
// baseline (speedup 1.0000x reference)
#include <cuda_runtime.h>
#include <math.h>

#define NN   10000
#define GG   200
#define ELn  160000
#define EGn  500000
#define SS   256
#define NAn  16
#define NBn  5

// ---- output offsets (floats) ----
#define OFF_CP   0
#define OFF_CE0  30000
#define OFF_AP   60000
#define OFF_AE   220000
#define OFF_BP   380000
#define OFF_BE   2880000
#define OFF_DL   5380000
#define OFF_RNL  5540000
#define OFF_AG   6020000
#define OFF_RNG  6520000

// ---- partitions ----
#define GBLK 2368                 // tail: global-edge blocks (4 warps each)
#define NS   (GBLK * 4)
#define LROWS 313                 // local-edge overlay rows on GEMM<1>
#define GROWS 977                 // geometry overlay rows on GEMM<0>
#define AROWS 625                 // atoms overlay rows on GEMM<0> (625*2 blocks * 8 warps = 10000)

typedef unsigned long long ull;

// ---- packed f32x2 helpers (sm_103a) ----
__device__ __forceinline__ ull f2pk(float lo, float hi) {
    ull r; asm("mov.b64 %0, {%1, %2};" : "=l"(r) : "f"(lo), "f"(hi)); return r;
}
__device__ __forceinline__ void f2upk(ull v, float& lo, float& hi) {
    asm("mov.b64 {%0, %1}, %2;" : "=f"(lo), "=f"(hi) : "l"(v));
}
__device__ __forceinline__ ull f2fma(ull a, ull b, ull c) {
    ull d; asm("fma.rn.f32x2 %0, %1, %2, %3;" : "=l"(d) : "l"(a), "l"(b), "l"(c)); return d;
}
__device__ __forceinline__ ull f2add(ull a, ull b) {
    ull d; asm("add.rn.f32x2 %0, %1, %2;" : "=l"(d) : "l"(a), "l"(b)); return d;
}

__device__ __forceinline__ int lbound(const int* __restrict__ a, int n, int v) {
    int lo = 0, hi = n;
    while (lo < hi) { int m = (lo + hi) >> 1; if (a[m] < v) lo = m + 1; else hi = m; }
    return lo;
}

// ---- scratch ----
__device__ float g_sum[GG * 3];
__device__ float g_cnt[GG];
__device__ float g_temb2[GG * SS];
__device__ float g_Wc[NAn * SS];
__device__ float g_hbias[SS];      // 0.5 * b_b0
__device__ float g_posc[NN * 3];
__device__ float g_db[EGn];
__device__ float g_bufA[NN * SS];
__device__ float g_bufB[NN * SS];

// ============================================================
// Launch 1 — k_pre: temb2 / Wc / hbias / per-graph pos sums
// blocks: [0,GG) temb2, [GG,GG+NAn) Wc, GG+NAn hbias,
//         [GG+NAn+1, GG+NAn+1+GG) graph sums (sorted batch, no atomics)
// ============================================================
__global__ void __launch_bounds__(256) k_pre(const float* __restrict__ t,
                                             const float* __restrict__ W_time,
                                             const float* __restrict__ b_time,
                                             const float* __restrict__ b_atom,
                                             const float* __restrict__ W_at,
                                             const float* __restrict__ b_at,
                                             const float* __restrict__ W_atom,
                                             const float* __restrict__ b_b0,
                                             const float* __restrict__ pos,
                                             const int* __restrict__ batch) {
    int b = blockIdx.x;
    int c = threadIdx.x;
    if (b < GG) {
        __shared__ float tin[SS];
        tin[c] = fmaf(t[b], W_time[c], b_time[c]) + b_atom[c];
        __syncthreads();
        float a0 = 0.f, a1 = 0.f, a2 = 0.f, a3 = 0.f;
#pragma unroll 4
        for (int k = 0; k < SS; k += 4) {
            a0 = fmaf(tin[k + 0], W_at[(k + 0) * SS + c], a0);
            a1 = fmaf(tin[k + 1], W_at[(k + 1) * SS + c], a1);
            a2 = fmaf(tin[k + 2], W_at[(k + 2) * SS + c], a2);
            a3 = fmaf(tin[k + 3], W_at[(k + 3) * SS + c], a3);
        }
        g_temb2[b * SS + c] = (a0 + a1) + (a2 + a3) + b_at[c];
    } else if (b < GG + NAn) {
        int r = b - GG;
        __shared__ float arow[SS];
        arow[c] = W_atom[r * SS + c];
        __syncthreads();
        float a0 = 0.f, a1 = 0.f, a2 = 0.f, a3 = 0.f;
#pragma unroll 4
        for (int k = 0; k < SS; k += 4) {
            a0 = fmaf(arow[k + 0], W_at[(k + 0) * SS + c], a0);
            a1 = fmaf(arow[k + 1], W_at[(k + 1) * SS + c], a1);
            a2 = fmaf(arow[k + 2], W_at[(k + 2) * SS + c], a2);
            a3 = fmaf(arow[k + 3], W_at[(k + 3) * SS + c], a3);
        }
        g_Wc[r * SS + c] = (a0 + a1) + (a2 + a3);
    } else if (b == GG + NAn) {
        g_hbias[c] = 0.5f * b_b0[c];
    } else {
        // per-graph pos sum over sorted batch range
        int g = b - (GG + NAn + 1);
        int lo = lbound(batch, NN, g);
        int hi = lbound(batch, NN, g + 1);
        float sx = 0.f, sy = 0.f, sz = 0.f;
        for (int n = lo + c; n < hi; n += 256) {
            sx += pos[n * 3 + 0];
            sy += pos[n * 3 + 1];
            sz += pos[n * 3 + 2];
        }
#pragma unroll
        for (int off = 16; off > 0; off >>= 1) {
            sx += __shfl_xor_sync(0xffffffffu, sx, off);
            sy += __shfl_xor_sync(0xffffffffu, sy, off);
            sz += __shfl_xor_sync(0xffffffffu, sz, off);
        }
        __shared__ float red[8][3];
        int w = c >> 5, lane = c & 31;
        if (lane == 0) { red[w][0] = sx; red[w][1] = sy; red[w][2] = sz; }
        __syncthreads();
        if (c == 0) {
            float tx = 0.f, ty = 0.f, tz = 0.f;
#pragma unroll
            for (int q = 0; q < 8; q++) { tx += red[q][0]; ty += red[q][1]; tz += red[q][2]; }
            g_sum[g * 3 + 0] = tx;
            g_sum[g * 3 + 1] = ty;
            g_sum[g * 3 + 2] = tz;
            g_cnt[g] = (float)(hi - lo);
        }
    }
}

// ============================================================
// Launch 2 — k_center_h2
// ============================================================
__global__ void __launch_bounds__(256) k_center_h2(const float* __restrict__ pos,
                                                   const int* __restrict__ batch,
                                                   const float* __restrict__ x,
                                                   float* __restrict__ out) {
    if (blockIdx.x < 40) {
        int n = blockIdx.x * 256 + threadIdx.x;
        if (n >= NN) return;
        int b = batch[n];
        float inv = 1.0f / fmaxf(g_cnt[b], 1.0f);
#pragma unroll
        for (int k = 0; k < 3; k++) {
            float v = pos[n * 3 + k] - g_sum[b * 3 + k] * inv;
            g_posc[n * 3 + k] = v;
            out[OFF_CP + n * 3 + k] = v;
            out[OFF_CE0 + n * 3 + k] = 0.f;
        }
    } else {
        int n = blockIdx.x - 40;
        int c = threadIdx.x;
        __shared__ float xs[NAn];
        __shared__ int bsh;
        if (c < NAn) xs[c] = x[n * NAn + c];
        if (c == 0) bsh = batch[n];
        __syncthreads();
        float acc = g_temb2[bsh * SS + c];
#pragma unroll
        for (int k = 0; k < NAn; k++) acc = fmaf(xs[k], g_Wc[k * SS + c], acc);
        g_bufA[n * SS + c] = acc;
    }
}

// ============================================================
// Launches 3,4 — fp32 GEMM (256-thread, 64x128, BK=16, dbl-buffer,
// packed f32x2). WORK: 1 = local-edge overlay,
//                 2 = geometry overlay + atoms overlay.
// ============================================================
template <int ACT, int WORK>
__global__ void __launch_bounds__(256) k_gemm64(const float* __restrict__ A,
                                                const float* __restrict__ W,
                                                const float* __restrict__ bias,
                                                float* __restrict__ C,
                                                const int* __restrict__ eil,
                                                const int* __restrict__ eig,
                                                const float* __restrict__ W_atoms,
                                                const float* __restrict__ b_atoms,
                                                float* __restrict__ out) {
    if (WORK == 1 && blockIdx.y >= 157) {
        // ---- local edge attrs overlay ----
        int e = (blockIdx.y - 157) * 512 + blockIdx.x * 256 + threadIdx.x;
        if (e >= ELn) return;
        int s = eil[e];
        int tg = eil[ELn + e];
        float rx = g_posc[tg * 3 + 0] - g_posc[s * 3 + 0];
        float ry = g_posc[tg * 3 + 1] - g_posc[s * 3 + 1];
        float rz = g_posc[tg * 3 + 2] - g_posc[s * 3 + 2];
        float ss = rx * rx + ry * ry + rz * rz;
        float sc = fmaxf(ss, 1e-6f);
        out[OFF_DL + e] = sqrtf(sc);
        float inv = rsqrtf(sc);
        out[OFF_RNL + 3 * e + 0] = rx * inv;
        out[OFF_RNL + 3 * e + 1] = ry * inv;
        out[OFF_RNL + 3 * e + 2] = rz * inv;
        return;
    }
    if (WORK == 2 && blockIdx.y >= 157) {
        int yy = blockIdx.y - 157;
        if (yy < GROWS) {
            // ---- global edge geometry overlay: a_g, rn_g, d -> g_db ----
            int e = yy * 512 + blockIdx.x * 256 + threadIdx.x;
            if (e >= EGn) return;
            int j = eig[e];
            int i = eig[EGn + e];
            float pix = g_posc[i * 3 + 0], piy = g_posc[i * 3 + 1], piz = g_posc[i * 3 + 2];
            float pjx = g_posc[j * 3 + 0], pjy = g_posc[j * 3 + 1], pjz = g_posc[j * 3 + 2];
            float rx = pix - pjx, ry = piy - pjy, rz = piz - pjz;
            float ss = rx * rx + ry * ry + rz * rz;
            g_db[e] = sqrtf(ss);
            out[OFF_AG + e] = pix * pjx + piy * pjy + piz * pjz;
            float inv = rsqrtf(fmaxf(ss, 1e-6f));
            out[OFF_RNG + 3 * e + 0] = rx * inv;
            out[OFF_RNG + 3 * e + 1] = ry * inv;
            out[OFF_RNG + 3 * e + 2] = rz * inv;
        } else {
            // ---- atoms overlay: warp per node (h3 = this GEMM's input A) ----
            int lane = threadIdx.x & 31;
            int w = (((yy - GROWS) * 2 + blockIdx.x) << 3) + (threadIdx.x >> 5);
            if (w >= NN) return;
            float acc = b_atoms[lane];
            for (int k0 = 0; k0 < SS; k0 += 32) {
                float hv = A[(size_t)w * SS + k0 + lane];
#pragma unroll
                for (int kk = 0; kk < 32; kk++) {
                    float h = __shfl_sync(0xffffffffu, hv, kk);
                    acc = fmaf(h, W_atoms[(k0 + kk) * 32 + lane], acc);
                }
            }
            if (lane < NAn) out[OFF_AE + w * NAn + lane] = acc;
            else            out[OFF_AP + w * NAn + (lane - NAn)] = acc;
        }
        return;
    }

    __shared__ float As[2][16][68];
    __shared__ float Bs[2][16][128];
    const int tid = threadIdx.x;
    const int row0 = blockIdx.y * 64;
    const int col0 = blockIdx.x * 128;
    const int ar = tid >> 2;
    const int ak = (tid & 3) * 4;
    const int bk = tid >> 4;
    const int bc = (tid & 15) * 8;
    const int ty = tid >> 4;
    const int tx = tid & 15;
    const int arow = row0 + ar;

    {
        float4 av = make_float4(0.f, 0.f, 0.f, 0.f);
        if (arow < NN) av = *(const float4*)&A[(size_t)arow * SS + ak];
        As[0][ak + 0][ar] = av.x;
        As[0][ak + 1][ar] = av.y;
        As[0][ak + 2][ar] = av.z;
        As[0][ak + 3][ar] = av.w;
        *(float4*)&Bs[0][bk][bc]     = *(const float4*)&W[(size_t)bk * SS + col0 + bc];
        *(float4*)&Bs[0][bk][bc + 4] = *(const float4*)&W[(size_t)bk * SS + col0 + bc + 4];
    }
    __syncthreads();

    ull accp[4][4];
#pragma unroll
    for (int i = 0; i < 4; i++)
#pragma unroll
        for (int m = 0; m < 4; m++) accp[i][m] = 0ull;

    for (int k0 = 0; k0 < SS; k0 += 16) {
        const int buf = (k0 >> 4) & 1;
        const bool more = (k0 + 16 < SS);
        float4 nav = make_float4(0.f, 0.f, 0.f, 0.f);
        float4 nbv0, nbv1;
        if (more) {
            if (arow < NN) nav = *(const float4*)&A[(size_t)arow * SS + k0 + 16 + ak];
            nbv0 = *(const float4*)&W[(size_t)(k0 + 16 + bk) * SS + col0 + bc];
            nbv1 = *(const float4*)&W[(size_t)(k0 + 16 + bk) * SS + col0 + bc + 4];
        }
#pragma unroll
        for (int k = 0; k < 16; k++) {
            float4 a4 = *(const float4*)&As[buf][k][ty * 4];
            ulonglong2 b01 = *(const ulonglong2*)&Bs[buf][k][tx * 4];
            ulonglong2 b23 = *(const ulonglong2*)&Bs[buf][k][64 + tx * 4];
            ull ap0 = f2pk(a4.x, a4.x);
            ull ap1 = f2pk(a4.y, a4.y);
            ull ap2 = f2pk(a4.z, a4.z);
            ull ap3 = f2pk(a4.w, a4.w);
            accp[0][0] = f2fma(ap0, b01.x, accp[0][0]);
            accp[0][1] = f2fma(ap0, b01.y, accp[0][1]);
            accp[0][2] = f2fma(ap0, b23.x, accp[0][2]);
            accp[0][3] = f2fma(ap0, b23.y, accp[0][3]);
            accp[1][0] = f2fma(ap1, b01.x, accp[1][0]);
            accp[1][1] = f2fma(ap1, b01.y, accp[1][1]);
            accp[1][2] = f2fma(ap1, b23.x, accp[1][2]);
            accp[1][3] = f2fma(ap1, b23.y, accp[1][3]);
            accp[2][0] = f2fma(ap2, b01.x, accp[2][0]);
            accp[2][1] = f2fma(ap2, b01.y, accp[2][1]);
            accp[2][2] = f2fma(ap2, b23.x, accp[2][2]);
            accp[2][3] = f2fma(ap2, b23.y, accp[2][3]);
            accp[3][0] = f2fma(ap3, b01.x, accp[3][0]);
            accp[3][1] = f2fma(ap3, b01.y, accp[3][1]);
            accp[3][2] = f2fma(ap3, b23.x, accp[3][2]);
            accp[3][3] = f2fma(ap3, b23.y, accp[3][3]);
        }
        if (more) {
            As[buf ^ 1][ak + 0][ar] = nav.x;
            As[buf ^ 1][ak + 1][ar] = nav.y;
            As[buf ^ 1][ak + 2][ar] = nav.z;
            As[buf ^ 1][ak + 3][ar] = nav.w;
            *(float4*)&Bs[buf ^ 1][bk][bc]     = nbv0;
            *(float4*)&Bs[buf ^ 1][bk][bc + 4] = nbv1;
            __syncthreads();
        }
    }

#pragma unroll
    for (int i = 0; i < 4; i++) {
        int row = row0 + ty * 4 + i;
        if (row >= NN) continue;
#pragma unroll
        for (int half = 0; half < 2; half++) {
            int col = col0 + half * 64 + tx * 4;
            float4 v;
            f2upk(accp[i][half * 2 + 0], v.x, v.y);
            f2upk(accp[i][half * 2 + 1], v.z, v.w);
            v.x += bias[col + 0];
            v.y += bias[col + 1];
            v.z += bias[col + 2];
            v.w += bias[col + 3];
            if (ACT == 1) {
                v.x = __fdividef(v.x, 1.0f + __expf(-v.x));
                v.y = __fdividef(v.y, 1.0f + __expf(-v.y));
                v.z = __fdividef(v.z, 1.0f + __expf(-v.z));
                v.w = __fdividef(v.w, 1.0f + __expf(-v.w));
            }
            *(float4*)&C[(size_t)row * SS + col] = v;
        }
    }
}

// ============================================================
// Launch 5 — k_tail: pure global-edge bonds MLP.
// Packed f32x2, paired-rcp sigmoid, split reduction,
// idx prefetch 2 ahead, u/db prefetch 1 ahead.
// ============================================================
__global__ void __launch_bounds__(128, 3) k_tail(const int* __restrict__ eig,
                                                 const float* __restrict__ u,
                                                 const float* __restrict__ W_b0,
                                                 const float* __restrict__ W_b1,
                                                 const float* __restrict__ b_b1,
                                                 float* __restrict__ out) {
    const int tid = threadIdx.x;
    const int lane = tid & 31;
    const int slot = blockIdx.x * 4 + (tid >> 5);
    const int ch0 = lane * 8;

    ull wb1p[8][5];
    ull wdp[4];
#pragma unroll
    for (int m = 0; m < 4; m++)
        wdp[m] = f2pk(W_b0[SS * SS + ch0 + 2 * m], W_b0[SS * SS + ch0 + 2 * m + 1]);
#pragma unroll
    for (int k = 0; k < 8; k++)
#pragma unroll
        for (int m = 0; m < 5; m++)
            wb1p[k][m] = f2pk(W_b1[(ch0 + k) * 10 + 2 * m],
                              W_b1[(ch0 + k) * 10 + 2 * m + 1]);
    float bb[5];
    {
        int base = (lane < 16) ? 0 : 5;
#pragma unroll
        for (int g = 0; g < 5; g++) bb[g] = b_b1[base + g];
    }

    int e = slot;
    if (e >= EGn) return;
    int j1 = eig[e];
    int i1 = eig[EGn + e];
    ulonglong2 UA0 = *(const ulonglong2*)(u + (size_t)i1 * SS + ch0);
    ulonglong2 UA1 = *(const ulonglong2*)(u + (size_t)i1 * SS + ch0 + 4);
    ulonglong2 UC0 = *(const ulonglong2*)(u + (size_t)j1 * SS + ch0);
    ulonglong2 UC1 = *(const ulonglong2*)(u + (size_t)j1 * SS + ch0 + 4);
    float db1 = g_db[e];
    int e2 = e + NS;
    int j2 = 0, i2 = 0;
    if (e2 < EGn) { j2 = eig[e2]; i2 = eig[EGn + e2]; }

    while (e < EGn) {
        int e3 = e2 + NS;
        int j3 = 0, i3 = 0;
        if (e3 < EGn) { j3 = eig[e3]; i3 = eig[EGn + e3]; }
        ulonglong2 UB0 = make_ulonglong2(0, 0), UB1 = UB0, UD0 = UB0, UD1 = UB0;
        float db2 = 0.f;
        if (e2 < EGn) {
            UB0 = *(const ulonglong2*)(u + (size_t)i2 * SS + ch0);
            UB1 = *(const ulonglong2*)(u + (size_t)i2 * SS + ch0 + 4);
            UD0 = *(const ulonglong2*)(u + (size_t)j2 * SS + ch0);
            UD1 = *(const ulonglong2*)(u + (size_t)j2 * SS + ch0 + 4);
            db2 = g_db[e2];
        }

        ull dbp = f2pk(db1, db1);
        ull prep[4];
        prep[0] = f2fma(dbp, wdp[0], f2add(UA0.x, UC0.x));
        prep[1] = f2fma(dbp, wdp[1], f2add(UA0.y, UC0.y));
        prep[2] = f2fma(dbp, wdp[2], f2add(UA1.x, UC1.x));
        prep[3] = f2fma(dbp, wdp[3], f2add(UA1.y, UC1.y));
        float pre[8];
        f2upk(prep[0], pre[0], pre[1]);
        f2upk(prep[1], pre[2], pre[3]);
        f2upk(prep[2], pre[4], pre[5]);
        f2upk(prep[3], pre[6], pre[7]);

        ull accp[5] = {0ull, 0ull, 0ull, 0ull, 0ull};
#pragma unroll
        for (int k = 0; k < 8; k += 2) {
            float t0 = __expf(-pre[k]);
            float t1 = __expf(-pre[k + 1]);
            float a0 = 1.0f + t0;
            float a1 = 1.0f + t1;
            float r = __fdividef(1.0f, a0 * a1);
            float hv0 = pre[k] * (r * a1);
            float hv1 = pre[k + 1] * (r * a0);
            ull hvp0 = f2pk(hv0, hv0);
            ull hvp1 = f2pk(hv1, hv1);
#pragma unroll
            for (int m = 0; m < 5; m++) {
                accp[m] = f2fma(hvp0, wb1p[k][m], accp[m]);
                accp[m] = f2fma(hvp1, wb1p[k + 1][m], accp[m]);
            }
        }

        float acc[10];
#pragma unroll
        for (int m = 0; m < 5; m++) f2upk(accp[m], acc[2 * m], acc[2 * m + 1]);

#pragma unroll
        for (int o = 0; o < 10; o++)
            acc[o] += __shfl_xor_sync(0xffffffffu, acc[o], 16);
        float v[5];
#pragma unroll
        for (int g = 0; g < 5; g++) v[g] = (lane < 16) ? acc[g] : acc[g + 5];
#pragma unroll
        for (int off = 8; off > 0; off >>= 1) {
#pragma unroll
            for (int g = 0; g < 5; g++)
                v[g] += __shfl_xor_sync(0xffffffffu, v[g], off);
        }
        if (lane == 0) {
#pragma unroll
            for (int g = 0; g < 5; g++)
                out[OFF_BP + (size_t)e * 5 + g] = v[g] + bb[g];
        } else if (lane == 16) {
#pragma unroll
            for (int g = 0; g < 5; g++)
                out[OFF_BE + (size_t)e * 5 + g] = v[g] + bb[g];
        }

        e = e2; i1 = i2; j1 = j2;
        UA0 = UB0; UA1 = UB1; UC0 = UD0; UC1 = UD1;
        db1 = db2;
        e2 = e3; i2 = i3; j2 = j3;
    }
}

// ============================================================
// Host launcher
// ============================================================
extern "C" void kernel_launch(void* const* d_in, const int* in_sizes, int n_in,
                              void* d_out, int out_size) {
    int iX, iT, iPOS, iWT, iBT, iWA, iBA, iWAT, iBAT, iWSH, iBSH,
        iWB0, iBB0, iWB1, iBB1, iWATM, iBATM, iEIL, iEIG, iBATCH;
    if (in_sizes[3] == 2 * ELn) {
        iX = 0; iT = 1; iPOS = 2; iEIL = 3; iEIG = 4; iBATCH = 6;
        iWT = 7; iBT = 8; iWA = 9; iBA = 10; iWAT = 11; iBAT = 12;
        iWSH = 13; iBSH = 14; iWB0 = 15; iBB0 = 16; iWB1 = 17; iBB1 = 18;
        iWATM = 20; iBATM = 21;
    } else {
        iX = 0; iT = 1; iPOS = 2; iWT = 4; iBT = 5; iWA = 6; iBA = 7;
        iWAT = 8; iBAT = 9; iWSH = 10; iBSH = 11; iWB0 = 12; iBB0 = 13;
        iWB1 = 14; iBB1 = 15; iWATM = 17; iBATM = 18;
        iEIL = 19; iEIG = 20; iBATCH = 21;
    }

    const float* x       = (const float*)d_in[iX];
    const float* t       = (const float*)d_in[iT];
    const float* pos     = (const float*)d_in[iPOS];
    const float* W_time  = (const float*)d_in[iWT];
    const float* b_time  = (const float*)d_in[iBT];
    const float* W_atom  = (const float*)d_in[iWA];
    const float* b_atom  = (const float*)d_in[iBA];
    const float* W_at    = (const float*)d_in[iWAT];
    const float* b_at    = (const float*)d_in[iBAT];
    const float* W_sh    = (const float*)d_in[iWSH];
    const float* b_sh    = (const float*)d_in[iBSH];
    const float* W_b0    = (const float*)d_in[iWB0];
    const float* b_b0    = (const float*)d_in[iBB0];
    const float* W_b1    = (const float*)d_in[iWB1];
    const float* b_b1    = (const float*)d_in[iBB1];
    const float* W_atoms = (const float*)d_in[iWATM];
    const float* b_atoms = (const float*)d_in[iBATM];
    const int* eil       = (const int*)d_in[iEIL];
    const int* eig       = (const int*)d_in[iEIG];
    const int* batch     = (const int*)d_in[iBATCH];
    float* out = (float*)d_out;

    float *bufA, *bufB, *hbias;
    cudaGetSymbolAddress((void**)&bufA, g_bufA);
    cudaGetSymbolAddress((void**)&bufB, g_bufB);
    cudaGetSymbolAddress((void**)&hbias, g_hbias);

    // 1: temb2 / Wc / hbias / per-graph pos sums
    k_pre<<<GG + NAn + 1 + GG, 256>>>(t, W_time, b_time, b_atom, W_at, b_at,
                                      W_atom, b_b0, pos, batch);
    // 2: center + h2
    k_center_h2<<<40 + NN, 256>>>(pos, batch, x, out);
    // 3: h3 GEMM + local-edge overlay
    dim3 gg1(2, 157 + LROWS);
    k_gemm64<1, 1><<<gg1, 256>>>(bufA, W_sh, b_sh, bufB, eil, eig,
                                 W_atoms, b_atoms, out);
    // 4: u GEMM + geometry overlay + atoms overlay
    dim3 gg0(2, 157 + GROWS + AROWS);
    k_gemm64<0, 2><<<gg0, 256>>>(bufB, W_b0, hbias, bufA, eil, eig,
                                 W_atoms, b_atoms, out);
    // 5: tail — bonds MLP only
    k_tail<<<GBLK, 128>>>(eig, bufA, W_b0, W_b1, b_b1, out);
}

// round 16
// speedup vs baseline: 1.0466x; 1.0466x over previous
#include <cuda_runtime.h>
#include <math.h>

#define NN   10000
#define GG   200
#define ELn  160000
#define EGn  500000
#define SS   256
#define NAn  16
#define NBn  5

// ---- output offsets (floats) ----
#define OFF_CP   0
#define OFF_CE0  30000
#define OFF_AP   60000
#define OFF_AE   220000
#define OFF_BP   380000
#define OFF_BE   2880000
#define OFF_DL   5380000
#define OFF_RNL  5540000
#define OFF_AG   6020000
#define OFF_RNG  6520000

// ---- partitions ----
#define GBLK 2368                 // tail: global-edge blocks (4 warps each)
#define NS   (GBLK * 4)
#define ABLK 2500                 // tail: atoms blocks (4 nodes each)
#define LROWS 313                 // local-edge overlay rows on GEMM<1>
#define GROWS 977                 // geometry overlay rows on GEMM<0>

typedef unsigned long long ull;

// ---- packed f32x2 helpers (sm_103a) ----
__device__ __forceinline__ ull f2pk(float lo, float hi) {
    ull r; asm("mov.b64 %0, {%1, %2};" : "=l"(r) : "f"(lo), "f"(hi)); return r;
}
__device__ __forceinline__ void f2upk(ull v, float& lo, float& hi) {
    asm("mov.b64 {%0, %1}, %2;" : "=f"(lo), "=f"(hi) : "l"(v));
}
__device__ __forceinline__ ull f2fma(ull a, ull b, ull c) {
    ull d; asm("fma.rn.f32x2 %0, %1, %2, %3;" : "=l"(d) : "l"(a), "l"(b), "l"(c)); return d;
}
__device__ __forceinline__ ull f2add(ull a, ull b) {
    ull d; asm("add.rn.f32x2 %0, %1, %2;" : "=l"(d) : "l"(a), "l"(b)); return d;
}

__device__ __forceinline__ int lbound(const int* __restrict__ a, int n, int v) {
    int lo = 0, hi = n;
    while (lo < hi) { int m = (lo + hi) >> 1; if (a[m] < v) lo = m + 1; else hi = m; }
    return lo;
}

// ---- scratch ----
__device__ float g_sum[GG * 3];
__device__ float g_cnt[GG];
__device__ float g_temb2[GG * SS];
__device__ float g_Wc[NAn * SS];
__device__ float g_hbias[SS];      // 0.5 * b_b0
__device__ float g_posc[NN * 3];
__device__ float g_db[EGn];
__device__ float g_bufA[NN * SS];
__device__ float g_bufB[NN * SS];

// ============================================================
// Launch 1 — k_pre: temb2 / Wc / hbias / per-graph pos sums
// ============================================================
__global__ void __launch_bounds__(256) k_pre(const float* __restrict__ t,
                                             const float* __restrict__ W_time,
                                             const float* __restrict__ b_time,
                                             const float* __restrict__ b_atom,
                                             const float* __restrict__ W_at,
                                             const float* __restrict__ b_at,
                                             const float* __restrict__ W_atom,
                                             const float* __restrict__ b_b0,
                                             const float* __restrict__ pos,
                                             const int* __restrict__ batch) {
    int b = blockIdx.x;
    int c = threadIdx.x;
    if (b < GG) {
        __shared__ float tin[SS];
        tin[c] = fmaf(t[b], W_time[c], b_time[c]) + b_atom[c];
        __syncthreads();
        float a0 = 0.f, a1 = 0.f, a2 = 0.f, a3 = 0.f;
#pragma unroll 4
        for (int k = 0; k < SS; k += 4) {
            a0 = fmaf(tin[k + 0], W_at[(k + 0) * SS + c], a0);
            a1 = fmaf(tin[k + 1], W_at[(k + 1) * SS + c], a1);
            a2 = fmaf(tin[k + 2], W_at[(k + 2) * SS + c], a2);
            a3 = fmaf(tin[k + 3], W_at[(k + 3) * SS + c], a3);
        }
        g_temb2[b * SS + c] = (a0 + a1) + (a2 + a3) + b_at[c];
    } else if (b < GG + NAn) {
        int r = b - GG;
        __shared__ float arow[SS];
        arow[c] = W_atom[r * SS + c];
        __syncthreads();
        float a0 = 0.f, a1 = 0.f, a2 = 0.f, a3 = 0.f;
#pragma unroll 4
        for (int k = 0; k < SS; k += 4) {
            a0 = fmaf(arow[k + 0], W_at[(k + 0) * SS + c], a0);
            a1 = fmaf(arow[k + 1], W_at[(k + 1) * SS + c], a1);
            a2 = fmaf(arow[k + 2], W_at[(k + 2) * SS + c], a2);
            a3 = fmaf(arow[k + 3], W_at[(k + 3) * SS + c], a3);
        }
        g_Wc[r * SS + c] = (a0 + a1) + (a2 + a3);
    } else if (b == GG + NAn) {
        g_hbias[c] = 0.5f * b_b0[c];
    } else {
        // per-graph pos sum over sorted batch range (no atomics)
        int g = b - (GG + NAn + 1);
        int lo = lbound(batch, NN, g);
        int hi = lbound(batch, NN, g + 1);
        float sx = 0.f, sy = 0.f, sz = 0.f;
        for (int n = lo + c; n < hi; n += 256) {
            sx += pos[n * 3 + 0];
            sy += pos[n * 3 + 1];
            sz += pos[n * 3 + 2];
        }
#pragma unroll
        for (int off = 16; off > 0; off >>= 1) {
            sx += __shfl_xor_sync(0xffffffffu, sx, off);
            sy += __shfl_xor_sync(0xffffffffu, sy, off);
            sz += __shfl_xor_sync(0xffffffffu, sz, off);
        }
        __shared__ float red[8][3];
        int w = c >> 5, lane = c & 31;
        if (lane == 0) { red[w][0] = sx; red[w][1] = sy; red[w][2] = sz; }
        __syncthreads();
        if (c == 0) {
            float tx = 0.f, ty = 0.f, tz = 0.f;
#pragma unroll
            for (int q = 0; q < 8; q++) { tx += red[q][0]; ty += red[q][1]; tz += red[q][2]; }
            g_sum[g * 3 + 0] = tx;
            g_sum[g * 3 + 1] = ty;
            g_sum[g * 3 + 2] = tz;
            g_cnt[g] = (float)(hi - lo);
        }
    }
}

// ============================================================
// Launch 2 — k_center_h2
// ============================================================
__global__ void __launch_bounds__(256) k_center_h2(const float* __restrict__ pos,
                                                   const int* __restrict__ batch,
                                                   const float* __restrict__ x,
                                                   float* __restrict__ out) {
    if (blockIdx.x < 40) {
        int n = blockIdx.x * 256 + threadIdx.x;
        if (n >= NN) return;
        int b = batch[n];
        float inv = 1.0f / fmaxf(g_cnt[b], 1.0f);
#pragma unroll
        for (int k = 0; k < 3; k++) {
            float v = pos[n * 3 + k] - g_sum[b * 3 + k] * inv;
            g_posc[n * 3 + k] = v;
            out[OFF_CP + n * 3 + k] = v;
            out[OFF_CE0 + n * 3 + k] = 0.f;
        }
    } else {
        int n = blockIdx.x - 40;
        int c = threadIdx.x;
        __shared__ float xs[NAn];
        __shared__ int bsh;
        if (c < NAn) xs[c] = x[n * NAn + c];
        if (c == 0) bsh = batch[n];
        __syncthreads();
        float acc = g_temb2[bsh * SS + c];
#pragma unroll
        for (int k = 0; k < NAn; k++) acc = fmaf(xs[k], g_Wc[k * SS + c], acc);
        g_bufA[n * SS + c] = acc;
    }
}

// ============================================================
// Launches 3,4 — fp32 GEMM (256-thread, 64x128, BK=16, dbl-buffer,
// packed f32x2). WORK: 1 = local-edge overlay, 2 = geometry overlay.
// ============================================================
template <int ACT, int WORK>
__global__ void __launch_bounds__(256) k_gemm64(const float* __restrict__ A,
                                                const float* __restrict__ W,
                                                const float* __restrict__ bias,
                                                float* __restrict__ C,
                                                const int* __restrict__ eil,
                                                const int* __restrict__ eig,
                                                float* __restrict__ out) {
    if (WORK == 1 && blockIdx.y >= 157) {
        // ---- local edge attrs overlay ----
        int e = (blockIdx.y - 157) * 512 + blockIdx.x * 256 + threadIdx.x;
        if (e >= ELn) return;
        int s = eil[e];
        int tg = eil[ELn + e];
        float rx = g_posc[tg * 3 + 0] - g_posc[s * 3 + 0];
        float ry = g_posc[tg * 3 + 1] - g_posc[s * 3 + 1];
        float rz = g_posc[tg * 3 + 2] - g_posc[s * 3 + 2];
        float ss = rx * rx + ry * ry + rz * rz;
        float sc = fmaxf(ss, 1e-6f);
        out[OFF_DL + e] = sqrtf(sc);
        float inv = rsqrtf(sc);
        out[OFF_RNL + 3 * e + 0] = rx * inv;
        out[OFF_RNL + 3 * e + 1] = ry * inv;
        out[OFF_RNL + 3 * e + 2] = rz * inv;
        return;
    }
    if (WORK == 2 && blockIdx.y >= 157) {
        // ---- global edge geometry overlay: a_g, rn_g, d -> g_db ----
        int e = (blockIdx.y - 157) * 512 + blockIdx.x * 256 + threadIdx.x;
        if (e >= EGn) return;
        int j = eig[e];
        int i = eig[EGn + e];
        float pix = g_posc[i * 3 + 0], piy = g_posc[i * 3 + 1], piz = g_posc[i * 3 + 2];
        float pjx = g_posc[j * 3 + 0], pjy = g_posc[j * 3 + 1], pjz = g_posc[j * 3 + 2];
        float rx = pix - pjx, ry = piy - pjy, rz = piz - pjz;
        float ss = rx * rx + ry * ry + rz * rz;
        g_db[e] = sqrtf(ss);
        out[OFF_AG + e] = pix * pjx + piy * pjy + piz * pjz;
        float inv = rsqrtf(fmaxf(ss, 1e-6f));
        out[OFF_RNG + 3 * e + 0] = rx * inv;
        out[OFF_RNG + 3 * e + 1] = ry * inv;
        out[OFF_RNG + 3 * e + 2] = rz * inv;
        return;
    }

    __shared__ float As[2][16][68];
    __shared__ float Bs[2][16][128];
    const int tid = threadIdx.x;
    const int row0 = blockIdx.y * 64;
    const int col0 = blockIdx.x * 128;
    const int ar = tid >> 2;
    const int ak = (tid & 3) * 4;
    const int bk = tid >> 4;
    const int bc = (tid & 15) * 8;
    const int ty = tid >> 4;
    const int tx = tid & 15;
    const int arow = row0 + ar;

    {
        float4 av = make_float4(0.f, 0.f, 0.f, 0.f);
        if (arow < NN) av = *(const float4*)&A[(size_t)arow * SS + ak];
        As[0][ak + 0][ar] = av.x;
        As[0][ak + 1][ar] = av.y;
        As[0][ak + 2][ar] = av.z;
        As[0][ak + 3][ar] = av.w;
        *(float4*)&Bs[0][bk][bc]     = *(const float4*)&W[(size_t)bk * SS + col0 + bc];
        *(float4*)&Bs[0][bk][bc + 4] = *(const float4*)&W[(size_t)bk * SS + col0 + bc + 4];
    }
    __syncthreads();

    ull accp[4][4];
#pragma unroll
    for (int i = 0; i < 4; i++)
#pragma unroll
        for (int m = 0; m < 4; m++) accp[i][m] = 0ull;

    for (int k0 = 0; k0 < SS; k0 += 16) {
        const int buf = (k0 >> 4) & 1;
        const bool more = (k0 + 16 < SS);
        float4 nav = make_float4(0.f, 0.f, 0.f, 0.f);
        float4 nbv0, nbv1;
        if (more) {
            if (arow < NN) nav = *(const float4*)&A[(size_t)arow * SS + k0 + 16 + ak];
            nbv0 = *(const float4*)&W[(size_t)(k0 + 16 + bk) * SS + col0 + bc];
            nbv1 = *(const float4*)&W[(size_t)(k0 + 16 + bk) * SS + col0 + bc + 4];
        }
#pragma unroll
        for (int k = 0; k < 16; k++) {
            float4 a4 = *(const float4*)&As[buf][k][ty * 4];
            ulonglong2 b01 = *(const ulonglong2*)&Bs[buf][k][tx * 4];
            ulonglong2 b23 = *(const ulonglong2*)&Bs[buf][k][64 + tx * 4];
            ull ap0 = f2pk(a4.x, a4.x);
            ull ap1 = f2pk(a4.y, a4.y);
            ull ap2 = f2pk(a4.z, a4.z);
            ull ap3 = f2pk(a4.w, a4.w);
            accp[0][0] = f2fma(ap0, b01.x, accp[0][0]);
            accp[0][1] = f2fma(ap0, b01.y, accp[0][1]);
            accp[0][2] = f2fma(ap0, b23.x, accp[0][2]);
            accp[0][3] = f2fma(ap0, b23.y, accp[0][3]);
            accp[1][0] = f2fma(ap1, b01.x, accp[1][0]);
            accp[1][1] = f2fma(ap1, b01.y, accp[1][1]);
            accp[1][2] = f2fma(ap1, b23.x, accp[1][2]);
            accp[1][3] = f2fma(ap1, b23.y, accp[1][3]);
            accp[2][0] = f2fma(ap2, b01.x, accp[2][0]);
            accp[2][1] = f2fma(ap2, b01.y, accp[2][1]);
            accp[2][2] = f2fma(ap2, b23.x, accp[2][2]);
            accp[2][3] = f2fma(ap2, b23.y, accp[2][3]);
            accp[3][0] = f2fma(ap3, b01.x, accp[3][0]);
            accp[3][1] = f2fma(ap3, b01.y, accp[3][1]);
            accp[3][2] = f2fma(ap3, b23.x, accp[3][2]);
            accp[3][3] = f2fma(ap3, b23.y, accp[3][3]);
        }
        if (more) {
            As[buf ^ 1][ak + 0][ar] = nav.x;
            As[buf ^ 1][ak + 1][ar] = nav.y;
            As[buf ^ 1][ak + 2][ar] = nav.z;
            As[buf ^ 1][ak + 3][ar] = nav.w;
            *(float4*)&Bs[buf ^ 1][bk][bc]     = nbv0;
            *(float4*)&Bs[buf ^ 1][bk][bc + 4] = nbv1;
            __syncthreads();
        }
    }

#pragma unroll
    for (int i = 0; i < 4; i++) {
        int row = row0 + ty * 4 + i;
        if (row >= NN) continue;
#pragma unroll
        for (int half = 0; half < 2; half++) {
            int col = col0 + half * 64 + tx * 4;
            float4 v;
            f2upk(accp[i][half * 2 + 0], v.x, v.y);
            f2upk(accp[i][half * 2 + 1], v.z, v.w);
            v.x += bias[col + 0];
            v.y += bias[col + 1];
            v.z += bias[col + 2];
            v.w += bias[col + 3];
            if (ACT == 1) {
                v.x = __fdividef(v.x, 1.0f + __expf(-v.x));
                v.y = __fdividef(v.y, 1.0f + __expf(-v.y));
                v.z = __fdividef(v.z, 1.0f + __expf(-v.z));
                v.w = __fdividef(v.w, 1.0f + __expf(-v.w));
            }
            *(float4*)&C[(size_t)row * SS + col] = v;
        }
    }
}

// ============================================================
// Launch 5 — k_tail: global-edge bonds MLP + atoms.
// ============================================================
__global__ void __launch_bounds__(128, 3) k_tail(const int* __restrict__ eig,
                                                 const float* __restrict__ u,
                                                 const float* __restrict__ W_b0,
                                                 const float* __restrict__ W_b1,
                                                 const float* __restrict__ b_b1,
                                                 const float* __restrict__ h3,
                                                 const float* __restrict__ W_atoms,
                                                 const float* __restrict__ b_atoms,
                                                 float* __restrict__ out) {
    const int blk = blockIdx.x;
    const int tid = threadIdx.x;
    const int lane = tid & 31;

    if (blk < GBLK) {
        // ---------------- global edges (bonds MLP only) ----------------
        const int slot = blk * 4 + (tid >> 5);
        const int ch0 = lane * 8;

        ull wb1p[8][5];
        ull wdp[4];
#pragma unroll
        for (int m = 0; m < 4; m++)
            wdp[m] = f2pk(W_b0[SS * SS + ch0 + 2 * m], W_b0[SS * SS + ch0 + 2 * m + 1]);
#pragma unroll
        for (int k = 0; k < 8; k++)
#pragma unroll
            for (int m = 0; m < 5; m++)
                wb1p[k][m] = f2pk(W_b1[(ch0 + k) * 10 + 2 * m],
                                  W_b1[(ch0 + k) * 10 + 2 * m + 1]);
        float bb[5];
        {
            int base = (lane < 16) ? 0 : 5;
#pragma unroll
            for (int g = 0; g < 5; g++) bb[g] = b_b1[base + g];
        }

        int e = slot;
        if (e >= EGn) return;
        int j1 = eig[e];
        int i1 = eig[EGn + e];
        ulonglong2 UA0 = *(const ulonglong2*)(u + (size_t)i1 * SS + ch0);
        ulonglong2 UA1 = *(const ulonglong2*)(u + (size_t)i1 * SS + ch0 + 4);
        ulonglong2 UC0 = *(const ulonglong2*)(u + (size_t)j1 * SS + ch0);
        ulonglong2 UC1 = *(const ulonglong2*)(u + (size_t)j1 * SS + ch0 + 4);
        float db1 = g_db[e];
        int e2 = e + NS;
        int j2 = 0, i2 = 0;
        if (e2 < EGn) { j2 = eig[e2]; i2 = eig[EGn + e2]; }

        while (e < EGn) {
            int e3 = e2 + NS;
            int j3 = 0, i3 = 0;
            if (e3 < EGn) { j3 = eig[e3]; i3 = eig[EGn + e3]; }
            ulonglong2 UB0 = make_ulonglong2(0, 0), UB1 = UB0, UD0 = UB0, UD1 = UB0;
            float db2 = 0.f;
            if (e2 < EGn) {
                UB0 = *(const ulonglong2*)(u + (size_t)i2 * SS + ch0);
                UB1 = *(const ulonglong2*)(u + (size_t)i2 * SS + ch0 + 4);
                UD0 = *(const ulonglong2*)(u + (size_t)j2 * SS + ch0);
                UD1 = *(const ulonglong2*)(u + (size_t)j2 * SS + ch0 + 4);
                db2 = g_db[e2];
            }

            ull dbp = f2pk(db1, db1);
            ull prep[4];
            prep[0] = f2fma(dbp, wdp[0], f2add(UA0.x, UC0.x));
            prep[1] = f2fma(dbp, wdp[1], f2add(UA0.y, UC0.y));
            prep[2] = f2fma(dbp, wdp[2], f2add(UA1.x, UC1.x));
            prep[3] = f2fma(dbp, wdp[3], f2add(UA1.y, UC1.y));
            float pre[8];
            f2upk(prep[0], pre[0], pre[1]);
            f2upk(prep[1], pre[2], pre[3]);
            f2upk(prep[2], pre[4], pre[5]);
            f2upk(prep[3], pre[6], pre[7]);

            ull accp[5] = {0ull, 0ull, 0ull, 0ull, 0ull};
#pragma unroll
            for (int k = 0; k < 8; k += 2) {
                float t0 = __expf(-pre[k]);
                float t1 = __expf(-pre[k + 1]);
                float a0 = 1.0f + t0;
                float a1 = 1.0f + t1;
                float r = __fdividef(1.0f, a0 * a1);
                float hv0 = pre[k] * (r * a1);
                float hv1 = pre[k + 1] * (r * a0);
                ull hvp0 = f2pk(hv0, hv0);
                ull hvp1 = f2pk(hv1, hv1);
#pragma unroll
                for (int m = 0; m < 5; m++) {
                    accp[m] = f2fma(hvp0, wb1p[k][m], accp[m]);
                    accp[m] = f2fma(hvp1, wb1p[k + 1][m], accp[m]);
                }
            }

            float acc[10];
#pragma unroll
            for (int m = 0; m < 5; m++) f2upk(accp[m], acc[2 * m], acc[2 * m + 1]);

#pragma unroll
            for (int o = 0; o < 10; o++)
                acc[o] += __shfl_xor_sync(0xffffffffu, acc[o], 16);
            float v[5];
#pragma unroll
            for (int g = 0; g < 5; g++) v[g] = (lane < 16) ? acc[g] : acc[g + 5];
#pragma unroll
            for (int off = 8; off > 0; off >>= 1) {
#pragma unroll
                for (int g = 0; g < 5; g++)
                    v[g] += __shfl_xor_sync(0xffffffffu, v[g], off);
            }
            if (lane == 0) {
#pragma unroll
                for (int g = 0; g < 5; g++)
                    out[OFF_BP + (size_t)e * 5 + g] = v[g] + bb[g];
            } else if (lane == 16) {
#pragma unroll
                for (int g = 0; g < 5; g++)
                    out[OFF_BE + (size_t)e * 5 + g] = v[g] + bb[g];
            }

            e = e2; i1 = i2; j1 = j2;
            UA0 = UB0; UA1 = UB1; UC0 = UD0; UC1 = UD1;
            db1 = db2;
            e2 = e3; i2 = i3; j2 = j3;
        }
    } else {
        // ---------------- atoms ----------------
        int w = (blk - GBLK) * 4 + (tid >> 5);
        if (w >= NN) return;
        float acc = b_atoms[lane];
        for (int k0 = 0; k0 < SS; k0 += 32) {
            float hv = h3[(size_t)w * SS + k0 + lane];
#pragma unroll
            for (int kk = 0; kk < 32; kk++) {
                float h = __shfl_sync(0xffffffffu, hv, kk);
                acc = fmaf(h, W_atoms[(k0 + kk) * 32 + lane], acc);
            }
        }
        if (lane < NAn) out[OFF_AE + w * NAn + lane] = acc;
        else            out[OFF_AP + w * NAn + (lane - NAn)] = acc;
    }
}

// ============================================================
// Host launcher
// ============================================================
extern "C" void kernel_launch(void* const* d_in, const int* in_sizes, int n_in,
                              void* d_out, int out_size) {
    int iX, iT, iPOS, iWT, iBT, iWA, iBA, iWAT, iBAT, iWSH, iBSH,
        iWB0, iBB0, iWB1, iBB1, iWATM, iBATM, iEIL, iEIG, iBATCH;
    if (in_sizes[3] == 2 * ELn) {
        iX = 0; iT = 1; iPOS = 2; iEIL = 3; iEIG = 4; iBATCH = 6;
        iWT = 7; iBT = 8; iWA = 9; iBA = 10; iWAT = 11; iBAT = 12;
        iWSH = 13; iBSH = 14; iWB0 = 15; iBB0 = 16; iWB1 = 17; iBB1 = 18;
        iWATM = 20; iBATM = 21;
    } else {
        iX = 0; iT = 1; iPOS = 2; iWT = 4; iBT = 5; iWA = 6; iBA = 7;
        iWAT = 8; iBAT = 9; iWSH = 10; iBSH = 11; iWB0 = 12; iBB0 = 13;
        iWB1 = 14; iBB1 = 15; iWATM = 17; iBATM = 18;
        iEIL = 19; iEIG = 20; iBATCH = 21;
    }

    const float* x       = (const float*)d_in[iX];
    const float* t       = (const float*)d_in[iT];
    const float* pos     = (const float*)d_in[iPOS];
    const float* W_time  = (const float*)d_in[iWT];
    const float* b_time  = (const float*)d_in[iBT];
    const float* W_atom  = (const float*)d_in[iWA];
    const float* b_atom  = (const float*)d_in[iBA];
    const float* W_at    = (const float*)d_in[iWAT];
    const float* b_at    = (const float*)d_in[iBAT];
    const float* W_sh    = (const float*)d_in[iWSH];
    const float* b_sh    = (const float*)d_in[iBSH];
    const float* W_b0    = (const float*)d_in[iWB0];
    const float* b_b0    = (const float*)d_in[iBB0];
    const float* W_b1    = (const float*)d_in[iWB1];
    const float* b_b1    = (const float*)d_in[iBB1];
    const float* W_atoms = (const float*)d_in[iWATM];
    const float* b_atoms = (const float*)d_in[iBATM];
    const int* eil       = (const int*)d_in[iEIL];
    const int* eig       = (const int*)d_in[iEIG];
    const int* batch     = (const int*)d_in[iBATCH];
    float* out = (float*)d_out;

    float *bufA, *bufB, *hbias;
    cudaGetSymbolAddress((void**)&bufA, g_bufA);
    cudaGetSymbolAddress((void**)&bufB, g_bufB);
    cudaGetSymbolAddress((void**)&hbias, g_hbias);

    // 1: temb2 / Wc / hbias / per-graph pos sums
    k_pre<<<GG + NAn + 1 + GG, 256>>>(t, W_time, b_time, b_atom, W_at, b_at,
                                      W_atom, b_b0, pos, batch);
    // 2: center + h2
    k_center_h2<<<40 + NN, 256>>>(pos, batch, x, out);
    // 3: h3 GEMM + local-edge overlay
    dim3 gg1(2, 157 + LROWS);
    k_gemm64<1, 1><<<gg1, 256>>>(bufA, W_sh, b_sh, bufB, eil, eig, out);
    // 4: u GEMM + geometry overlay
    dim3 gg0(2, 157 + GROWS);
    k_gemm64<0, 2><<<gg0, 256>>>(bufB, W_b0, hbias, bufA, eil, eig, out);
    // 5: tail — bonds MLP + atoms
    k_tail<<<GBLK + ABLK, 128>>>(eig, bufA, W_b0, W_b1, b_b1,
                                 bufB, W_atoms, b_atoms, out);
}